// round 9
// baseline (speedup 1.0000x reference)
#include <cuda_runtime.h>
#include <cstdint>

// INT8BertEmbeddings R9 = R5 + cp.async word-row gather pipeline.
//  Kernel 1: precompute fused pos+type table in fp32 (3 MB device scratch).
//  Kernel 2: warp-per-token. The random word-table gather goes through
//   cp.async (LDGSTS) into a per-warp 2-stage smem buffer: all 6 16B copies
//   per token issue with zero register cost, and token i+1's copies are in
//   flight during token i's compute. Per-warp commit/wait only -- no
//   __syncthreads, no cross-lane smem dependencies (each lane reads exactly
//   the bytes it copied). pt-table rows stay LDG (streaming locality).

constexpr int H    = 768;
constexpr int VPR  = H / 4;      // 192 float4/int4 per row
constexpr int TPB  = 128;        // 4 warps
constexpr int NW   = TPB / 32;
constexpr int TOKW = 4;          // tokens per warp
constexpr int TOK_PER_CTA = NW * TOKW;   // 16
constexpr int CH   = VPR / 32;   // 6 chunks per warp per row
constexpr int ROWB = VPR * 16;   // 3072 bytes per word row

constexpr int MAX_T = 2;
constexpr int MAX_S = 512;
__device__ float4 g_pt_tab[MAX_T * MAX_S * VPR];   // 3 MB fused pos+type table

__device__ __forceinline__ void store_streaming(float4* addr, float4 v) {
    asm volatile("st.global.cs.v4.f32 [%0], {%1, %2, %3, %4};"
                 :: "l"(addr), "f"(v.x), "f"(v.y), "f"(v.z), "f"(v.w)
                 : "memory");
}

__device__ __forceinline__ uint32_t smem_u32(const void* p) {
    uint32_t a;
    asm("{ .reg .u64 t; cvta.to.shared.u64 t, %1; cvt.u32.u64 %0, t; }"
        : "=r"(a) : "l"(p));
    return a;
}

__device__ __forceinline__ void cp_async16(uint32_t smem_dst, const void* gmem_src) {
    asm volatile("cp.async.cg.shared.global [%0], [%1], 16;"
                 :: "r"(smem_dst), "l"(gmem_src) : "memory");
}

__device__ __forceinline__ void cp_commit() {
    asm volatile("cp.async.commit_group;" ::: "memory");
}

template <int N>
__device__ __forceinline__ void cp_wait() {
    asm volatile("cp.async.wait_group %0;" :: "n"(N) : "memory");
}

__global__ __launch_bounds__(VPR) void build_pt_kernel(
    const int4* __restrict__ pos_table, const float* __restrict__ pos_scale,
    const int4* __restrict__ type_table, const float* __restrict__ type_scale,
    int S, int T)
{
    const int row = blockIdx.x;          // 0 .. T*S-1
    const int tt  = row / S;
    const int s   = row % S;
    const int tid = threadIdx.x;
    const float ps = __ldg(pos_scale);
    const float ts = __ldg(type_scale);

    const int4 p = __ldg(&pos_table [(size_t)s  * VPR + tid]);
    const int4 t = __ldg(&type_table[(size_t)tt * VPR + tid]);
    float4 o;
    o.x = (float)p.x * ps + (float)t.x * ts;
    o.y = (float)p.y * ps + (float)t.y * ts;
    o.z = (float)p.z * ps + (float)t.z * ts;
    o.w = (float)p.w * ps + (float)t.w * ts;
    g_pt_tab[(size_t)row * VPR + tid] = o;
}

__global__ __launch_bounds__(TPB, 8) void bert_emb_ln_kernel(
    const int*  __restrict__ input_ids,
    const int*  __restrict__ token_type_ids,
    const int4* __restrict__ word_table,
    const float* __restrict__ word_scale,
    const float4* __restrict__ ln_w,
    const float4* __restrict__ ln_b,
    float4* __restrict__ out,
    int S, int n_tokens)
{
    const int lane = threadIdx.x & 31;
    const int warp = threadIdx.x >> 5;
    const int base = (blockIdx.x * NW + warp) * TOKW;

    // Per-warp private double buffer for word rows.
    __shared__ __align__(16) char s_word[NW][2][ROWB];

    const float ws = __ldg(word_scale);

    // Issue cp.async for one token's word row into the given stage.
    auto issue_word = [&](int token, int stage) {
        const int wrow = __ldg(&input_ids[token]);
        const char* src = (const char*)(word_table + (size_t)wrow * VPR);
        const uint32_t dst = smem_u32(&s_word[warp][stage][0]);
        #pragma unroll
        for (int c = 0; c < CH; ++c) {
            const int off = (c * 32 + lane) * 16;
            cp_async16(dst + off, src + off);
        }
        cp_commit();
    };

    if (base < n_tokens) issue_word(base, 0);

    #pragma unroll
    for (int i = 0; i < TOKW; ++i) {
        const int token = base + i;
        if (token >= n_tokens) return;

        const bool have_next = (i + 1 < TOKW) && (token + 1 < n_tokens);
        if (have_next) {
            issue_word(token + 1, (i + 1) & 1);
            cp_wait<1>();   // current token's group done; next stays in flight
        } else {
            cp_wait<0>();
        }

        const int trow = __ldg(&token_type_ids[token]);
        const int s    = token % S;
        const float4* pp = g_pt_tab + ((size_t)trow * S + s) * VPR;
        const int4* wsm = (const int4*)&s_word[warp][i & 1][0];

        float4 e[CH];
        float sum = 0.f, sq = 0.f;
        #pragma unroll
        for (int c = 0; c < CH; ++c) {
            const int col = c * 32 + lane;
            const int4   w = wsm[col];       // LDS.128, conflict-free
            const float4 q = pp[col];
            e[c].x = (float)w.x * ws + q.x;
            e[c].y = (float)w.y * ws + q.y;
            e[c].z = (float)w.z * ws + q.z;
            e[c].w = (float)w.w * ws + q.w;
            sum += e[c].x + e[c].y + e[c].z + e[c].w;
            sq  += e[c].x * e[c].x + e[c].y * e[c].y
                 + e[c].z * e[c].z + e[c].w * e[c].w;
        }

        // Pure warp reduction (full row lives in this warp).
        #pragma unroll
        for (int off = 16; off > 0; off >>= 1) {
            sum += __shfl_xor_sync(0xFFFFFFFFu, sum, off);
            sq  += __shfl_xor_sync(0xFFFFFFFFu, sq,  off);
        }

        const float inv_h = 1.0f / (float)H;
        const float mean  = sum * inv_h;
        float var = sq * inv_h - mean * mean;
        var = fmaxf(var, 0.0f);

        // The reference's 8-iteration Newton-Raphson sqrt converges to
        // sqrt(var) to full fp32 precision for this data's var range.
        const float std_approx = sqrtf(var);
        const float inv_std = __fdividef(1.0f, std_approx + 1e-12f);

        float4* orow = out + (size_t)token * VPR;
        #pragma unroll
        for (int c = 0; c < CH; ++c) {
            const int col = c * 32 + lane;
            const float4 g = __ldg(&ln_w[col]);
            const float4 b = __ldg(&ln_b[col]);
            float4 o;
            o.x = g.x * ((e[c].x - mean) * inv_std) + b.x;
            o.y = g.y * ((e[c].y - mean) * inv_std) + b.y;
            o.z = g.z * ((e[c].z - mean) * inv_std) + b.z;
            o.w = g.w * ((e[c].w - mean) * inv_std) + b.w;
            store_streaming(&orow[col], o);
        }
    }
}

extern "C" void kernel_launch(void* const* d_in, const int* in_sizes, int n_in,
                              void* d_out, int out_size)
{
    const int*   input_ids      = (const int*)  d_in[0];
    const int*   token_type_ids = (const int*)  d_in[1];
    const int*   word_table     = (const int*)  d_in[2];
    const float* word_scale     = (const float*)d_in[3];
    const int*   pos_table      = (const int*)  d_in[4];
    const float* pos_scale      = (const float*)d_in[5];
    const int*   type_table     = (const int*)  d_in[6];
    const float* type_scale     = (const float*)d_in[7];
    const float* ln_w           = (const float*)d_in[8];
    const float* ln_b           = (const float*)d_in[9];

    const int n_tokens = in_sizes[0];       // B*S
    const int S        = in_sizes[4] / H;   // 512
    const int T        = in_sizes[6] / H;   // 2

    build_pt_kernel<<<T * S, VPR>>>(
        (const int4*)pos_table, pos_scale,
        (const int4*)type_table, type_scale, S, T);

    const int grid = (n_tokens + TOK_PER_CTA - 1) / TOK_PER_CTA;
    bert_emb_ln_kernel<<<grid, TPB>>>(
        input_ids, token_type_ids,
        (const int4*)word_table, word_scale,
        (const float4*)ln_w, (const float4*)ln_b,
        (float4*)d_out, S, n_tokens);
}

// round 11
// speedup vs baseline: 1.1097x; 1.1097x over previous
#include <cuda_runtime.h>
#include <cstdint>

// INT8BertEmbeddings R11 (= R10 resubmit; R10 hit an infra failure).
// R5 best structure + ln_w/ln_b register-cached across the warp's 4 tokens.
// Theory: kernel is L1tex-wavefront bound; per-token ln reloads were 48 of
// ~120 wavefronts per token. Caching them (48 regs, loaded once, amortized
// over 4 tokens) cuts per-token L1 work ~40% at an occupancy cost that R7
// showed to be irrelevant (>40% occ buys nothing here).
//  Kernel 1: precompute fused pos+type table in fp32 (3 MB device scratch).
//  Kernel 2: warp-per-token, single pass, 24 elems/thread, no barriers.

constexpr int H    = 768;
constexpr int VPR  = H / 4;      // 192 float4/int4 per row
constexpr int TPB  = 128;        // 4 warps
constexpr int NW   = TPB / 32;
constexpr int TOKW = 4;          // tokens per warp
constexpr int TOK_PER_CTA = NW * TOKW;   // 16
constexpr int CH   = VPR / 32;   // 6 chunks per warp per row

constexpr int MAX_T = 2;
constexpr int MAX_S = 512;
__device__ float4 g_pt_tab[MAX_T * MAX_S * VPR];   // 3 MB fused pos+type table

__device__ __forceinline__ void store_streaming(float4* addr, float4 v) {
    asm volatile("st.global.cs.v4.f32 [%0], {%1, %2, %3, %4};"
                 :: "l"(addr), "f"(v.x), "f"(v.y), "f"(v.z), "f"(v.w)
                 : "memory");
}

__global__ __launch_bounds__(VPR) void build_pt_kernel(
    const int4* __restrict__ pos_table, const float* __restrict__ pos_scale,
    const int4* __restrict__ type_table, const float* __restrict__ type_scale,
    int S, int T)
{
    const int row = blockIdx.x;          // 0 .. T*S-1
    const int tt  = row / S;
    const int s   = row % S;
    const int tid = threadIdx.x;
    const float ps = __ldg(pos_scale);
    const float ts = __ldg(type_scale);

    const int4 p = __ldg(&pos_table [(size_t)s  * VPR + tid]);
    const int4 t = __ldg(&type_table[(size_t)tt * VPR + tid]);
    float4 o;
    o.x = (float)p.x * ps + (float)t.x * ts;
    o.y = (float)p.y * ps + (float)t.y * ts;
    o.z = (float)p.z * ps + (float)t.z * ts;
    o.w = (float)p.w * ps + (float)t.w * ts;
    g_pt_tab[(size_t)row * VPR + tid] = o;
}

__global__ __launch_bounds__(TPB, 5) void bert_emb_ln_kernel(
    const int*  __restrict__ input_ids,
    const int*  __restrict__ token_type_ids,
    const int4* __restrict__ word_table,
    const float* __restrict__ word_scale,
    const float4* __restrict__ ln_w,
    const float4* __restrict__ ln_b,
    float4* __restrict__ out,
    int S, int n_tokens)
{
    const int lane = threadIdx.x & 31;
    const int warp = threadIdx.x >> 5;
    const int base = (blockIdx.x * NW + warp) * TOKW;

    const float ws = __ldg(word_scale);

    // Register-cache ln params once per warp; amortized over TOKW tokens.
    float4 g[CH], b[CH];
    #pragma unroll
    for (int c = 0; c < CH; ++c) {
        g[c] = __ldg(&ln_w[c * 32 + lane]);
        b[c] = __ldg(&ln_b[c * 32 + lane]);
    }

    #pragma unroll
    for (int i = 0; i < TOKW; ++i) {
        const int token = base + i;
        if (token >= n_tokens) return;

        const int wrow = __ldg(&input_ids[token]);
        const int trow = __ldg(&token_type_ids[token]);
        const int s    = token % S;

        const int4*   wp = word_table + (size_t)wrow * VPR;
        const float4* pp = g_pt_tab + ((size_t)trow * S + s) * VPR;

        float4 e[CH];
        float sum = 0.f, sq = 0.f;
        #pragma unroll
        for (int c = 0; c < CH; ++c) {
            const int col = c * 32 + lane;
            const int4   w = __ldg(&wp[col]);
            const float4 q = pp[col];
            e[c].x = (float)w.x * ws + q.x;
            e[c].y = (float)w.y * ws + q.y;
            e[c].z = (float)w.z * ws + q.z;
            e[c].w = (float)w.w * ws + q.w;
            sum += e[c].x + e[c].y + e[c].z + e[c].w;
            sq  += e[c].x * e[c].x + e[c].y * e[c].y
                 + e[c].z * e[c].z + e[c].w * e[c].w;
        }

        // Pure warp reduction (full row lives in this warp).
        #pragma unroll
        for (int off = 16; off > 0; off >>= 1) {
            sum += __shfl_xor_sync(0xFFFFFFFFu, sum, off);
            sq  += __shfl_xor_sync(0xFFFFFFFFu, sq,  off);
        }

        const float inv_h = 1.0f / (float)H;
        const float mean  = sum * inv_h;
        float var = sq * inv_h - mean * mean;
        var = fmaxf(var, 0.0f);

        // The reference's 8-iteration Newton-Raphson sqrt converges to
        // sqrt(var) to full fp32 precision for this data's var range.
        const float std_approx = sqrtf(var);
        const float inv_std = __fdividef(1.0f, std_approx + 1e-12f);

        float4* orow = out + (size_t)token * VPR;
        #pragma unroll
        for (int c = 0; c < CH; ++c) {
            float4 o;
            o.x = g[c].x * ((e[c].x - mean) * inv_std) + b[c].x;
            o.y = g[c].y * ((e[c].y - mean) * inv_std) + b[c].y;
            o.z = g[c].z * ((e[c].z - mean) * inv_std) + b[c].z;
            o.w = g[c].w * ((e[c].w - mean) * inv_std) + b[c].w;
            store_streaming(&orow[c * 32 + lane], o);
        }
    }
}

extern "C" void kernel_launch(void* const* d_in, const int* in_sizes, int n_in,
                              void* d_out, int out_size)
{
    const int*   input_ids      = (const int*)  d_in[0];
    const int*   token_type_ids = (const int*)  d_in[1];
    const int*   word_table     = (const int*)  d_in[2];
    const float* word_scale     = (const float*)d_in[3];
    const int*   pos_table      = (const int*)  d_in[4];
    const float* pos_scale      = (const float*)d_in[5];
    const int*   type_table     = (const int*)  d_in[6];
    const float* type_scale     = (const float*)d_in[7];
    const float* ln_w           = (const float*)d_in[8];
    const float* ln_b           = (const float*)d_in[9];

    const int n_tokens = in_sizes[0];       // B*S
    const int S        = in_sizes[4] / H;   // 512
    const int T        = in_sizes[6] / H;   // 2

    build_pt_kernel<<<T * S, VPR>>>(
        (const int4*)pos_table, pos_scale,
        (const int4*)type_table, type_scale, S, T);

    const int grid = (n_tokens + TOK_PER_CTA - 1) / TOK_PER_CTA;
    bert_emb_ln_kernel<<<grid, TPB>>>(
        input_ids, token_type_ids,
        (const int4*)word_table, word_scale,
        (const float4*)ln_w, (const float4*)ln_b,
        (float4*)d_out, S, n_tokens);
}

// round 12
// speedup vs baseline: 1.1656x; 1.0504x over previous
#include <cuda_runtime.h>
#include <cstdint>

// INT8BertEmbeddings R12 = R5 structure + ln_w/ln_b cached in SHARED memory.
// R11 proved the ln-reload L1 traffic cut works (L1% 60->38, main kernel
// 35.4->33.7us) but paid 96 regs -> occ 23%. Moving the cache to smem keeps
// the L1tex wavefront cut (epilogue reads are LDS, not L1tex) while regs
// return to ~64 -> occ ~45-50%. One uniform __syncthreads at kernel start.
//  Kernel 1: precompute fused pos+type table in fp32 (3 MB device scratch).
//  Kernel 2: warp-per-token, single pass, 24 elems/thread.

constexpr int H    = 768;
constexpr int VPR  = H / 4;      // 192 float4/int4 per row
constexpr int TPB  = 128;        // 4 warps
constexpr int NW   = TPB / 32;
constexpr int TOKW = 4;          // tokens per warp
constexpr int TOK_PER_CTA = NW * TOKW;   // 16
constexpr int CH   = VPR / 32;   // 6 chunks per warp per row

constexpr int MAX_T = 2;
constexpr int MAX_S = 512;
__device__ float4 g_pt_tab[MAX_T * MAX_S * VPR];   // 3 MB fused pos+type table

__device__ __forceinline__ void store_streaming(float4* addr, float4 v) {
    asm volatile("st.global.cs.v4.f32 [%0], {%1, %2, %3, %4};"
                 :: "l"(addr), "f"(v.x), "f"(v.y), "f"(v.z), "f"(v.w)
                 : "memory");
}

__global__ __launch_bounds__(VPR) void build_pt_kernel(
    const int4* __restrict__ pos_table, const float* __restrict__ pos_scale,
    const int4* __restrict__ type_table, const float* __restrict__ type_scale,
    int S, int T)
{
    const int row = blockIdx.x;          // 0 .. T*S-1
    const int tt  = row / S;
    const int s   = row % S;
    const int tid = threadIdx.x;
    const float ps = __ldg(pos_scale);
    const float ts = __ldg(type_scale);

    const int4 p = __ldg(&pos_table [(size_t)s  * VPR + tid]);
    const int4 t = __ldg(&type_table[(size_t)tt * VPR + tid]);
    float4 o;
    o.x = (float)p.x * ps + (float)t.x * ts;
    o.y = (float)p.y * ps + (float)t.y * ts;
    o.z = (float)p.z * ps + (float)t.z * ts;
    o.w = (float)p.w * ps + (float)t.w * ts;
    g_pt_tab[(size_t)row * VPR + tid] = o;
}

__global__ __launch_bounds__(TPB, 8) void bert_emb_ln_kernel(
    const int*  __restrict__ input_ids,
    const int*  __restrict__ token_type_ids,
    const int4* __restrict__ word_table,
    const float* __restrict__ word_scale,
    const float4* __restrict__ ln_w,
    const float4* __restrict__ ln_b,
    float4* __restrict__ out,
    int S, int n_tokens)
{
    const int tid  = threadIdx.x;
    const int lane = tid & 31;
    const int warp = tid >> 5;
    const int base = (blockIdx.x * NW + warp) * TOKW;

    // Block-shared ln cache: loaded once per CTA, read via LDS (off the
    // L1tex wavefront path).
    __shared__ __align__(16) float4 s_g[VPR];
    __shared__ __align__(16) float4 s_b[VPR];
    #pragma unroll
    for (int c = 0; c < VPR / TPB + 1; ++c) {
        const int idx = c * TPB + tid;
        if (idx < VPR) {
            s_g[idx] = __ldg(&ln_w[idx]);
            s_b[idx] = __ldg(&ln_b[idx]);
        }
    }
    __syncthreads();   // uniform, reached by all threads exactly once

    const float ws = __ldg(word_scale);

    #pragma unroll
    for (int i = 0; i < TOKW; ++i) {
        const int token = base + i;
        if (token >= n_tokens) return;

        const int wrow = __ldg(&input_ids[token]);
        const int trow = __ldg(&token_type_ids[token]);
        const int s    = token % S;

        const int4*   wp = word_table + (size_t)wrow * VPR;
        const float4* pp = g_pt_tab + ((size_t)trow * S + s) * VPR;

        float4 e[CH];
        float sum = 0.f, sq = 0.f;
        #pragma unroll
        for (int c = 0; c < CH; ++c) {
            const int col = c * 32 + lane;
            const int4   w = __ldg(&wp[col]);
            const float4 q = pp[col];
            e[c].x = (float)w.x * ws + q.x;
            e[c].y = (float)w.y * ws + q.y;
            e[c].z = (float)w.z * ws + q.z;
            e[c].w = (float)w.w * ws + q.w;
            sum += e[c].x + e[c].y + e[c].z + e[c].w;
            sq  += e[c].x * e[c].x + e[c].y * e[c].y
                 + e[c].z * e[c].z + e[c].w * e[c].w;
        }

        // Pure warp reduction (full row lives in this warp).
        #pragma unroll
        for (int off = 16; off > 0; off >>= 1) {
            sum += __shfl_xor_sync(0xFFFFFFFFu, sum, off);
            sq  += __shfl_xor_sync(0xFFFFFFFFu, sq,  off);
        }

        const float inv_h = 1.0f / (float)H;
        const float mean  = sum * inv_h;
        float var = sq * inv_h - mean * mean;
        var = fmaxf(var, 0.0f);

        // The reference's 8-iteration Newton-Raphson sqrt converges to
        // sqrt(var) to full fp32 precision for this data's var range.
        const float std_approx = sqrtf(var);
        const float inv_std = __fdividef(1.0f, std_approx + 1e-12f);

        float4* orow = out + (size_t)token * VPR;
        #pragma unroll
        for (int c = 0; c < CH; ++c) {
            const int col = c * 32 + lane;
            const float4 g = s_g[col];   // LDS.128, conflict-free
            const float4 b = s_b[col];
            float4 o;
            o.x = g.x * ((e[c].x - mean) * inv_std) + b.x;
            o.y = g.y * ((e[c].y - mean) * inv_std) + b.y;
            o.z = g.z * ((e[c].z - mean) * inv_std) + b.z;
            o.w = g.w * ((e[c].w - mean) * inv_std) + b.w;
            store_streaming(&orow[col], o);
        }
    }
}

extern "C" void kernel_launch(void* const* d_in, const int* in_sizes, int n_in,
                              void* d_out, int out_size)
{
    const int*   input_ids      = (const int*)  d_in[0];
    const int*   token_type_ids = (const int*)  d_in[1];
    const int*   word_table     = (const int*)  d_in[2];
    const float* word_scale     = (const float*)d_in[3];
    const int*   pos_table      = (const int*)  d_in[4];
    const float* pos_scale      = (const float*)d_in[5];
    const int*   type_table     = (const int*)  d_in[6];
    const float* type_scale     = (const float*)d_in[7];
    const float* ln_w           = (const float*)d_in[8];
    const float* ln_b           = (const float*)d_in[9];

    const int n_tokens = in_sizes[0];       // B*S
    const int S        = in_sizes[4] / H;   // 512
    const int T        = in_sizes[6] / H;   // 2

    build_pt_kernel<<<T * S, VPR>>>(
        (const int4*)pos_table, pos_scale,
        (const int4*)type_table, type_scale, S, T);

    const int grid = (n_tokens + TOK_PER_CTA - 1) / TOK_PER_CTA;
    bert_emb_ln_kernel<<<grid, TPB>>>(
        input_ids, token_type_ids,
        (const int4*)word_table, word_scale,
        (const float4*)ln_w, (const float4*)ln_b,
        (float4*)d_out, S, n_tokens);
}

// round 13
// speedup vs baseline: 1.2622x; 1.0828x over previous
#include <cuda_runtime.h>
#include <cstdint>

// INT8BertEmbeddings R13: single kernel, s-major CTA mapping.
// Each CTA owns ONE sequence position s across 16 batches (4 warps x 4
// batches). The pos+type rows for this s (T=2 -> both type variants) are
// dequant-fused into smem ONCE per CTA, then reused by all 16 tokens:
//  - kills the per-token pt-table L1tex wavefronts (24 of 72 per token)
//  - kills the build_pt prepass kernel (+launch gap, ~3.3us fixed)
// ln_w/ln_b also smem-cached (R12 win). Warp-per-token, single pass,
// 24 elems/thread, one uniform __syncthreads after the smem fill.

constexpr int H    = 768;
constexpr int VPR  = H / 4;      // 192 float4/int4 per row
constexpr int TPB  = 128;        // 4 warps
constexpr int NW   = TPB / 32;
constexpr int TOKW = 4;          // batches per warp
constexpr int BPC  = NW * TOKW;  // 16 batches per CTA
constexpr int CH   = VPR / 32;   // 6 chunks per warp per row
constexpr int MAX_T = 2;

__device__ __forceinline__ void store_streaming(float4* addr, float4 v) {
    asm volatile("st.global.cs.v4.f32 [%0], {%1, %2, %3, %4};"
                 :: "l"(addr), "f"(v.x), "f"(v.y), "f"(v.z), "f"(v.w)
                 : "memory");
}

__global__ __launch_bounds__(TPB, 8) void bert_emb_ln_kernel(
    const int*  __restrict__ input_ids,
    const int*  __restrict__ token_type_ids,
    const int4* __restrict__ word_table,
    const float* __restrict__ word_scale,
    const int4* __restrict__ pos_table,
    const float* __restrict__ pos_scale,
    const int4* __restrict__ type_table,
    const float* __restrict__ type_scale,
    const float4* __restrict__ ln_w,
    const float4* __restrict__ ln_b,
    float4* __restrict__ out,
    int S, int B)
{
    const int tid  = threadIdx.x;
    const int lane = tid & 31;
    const int warp = tid >> 5;

    const int s  = blockIdx.x % S;           // sequence position for this CTA
    const int bg = blockIdx.x / S;           // batch group
    const int b0 = bg * BPC + warp * TOKW;   // first batch for this warp

    // smem: fused pos+type rows for this s (both type variants) + ln params.
    __shared__ __align__(16) float4 s_pt[MAX_T][VPR];
    __shared__ __align__(16) float4 s_g[VPR];
    __shared__ __align__(16) float4 s_b[VPR];

    {
        const float ps = __ldg(pos_scale);
        const float ts = __ldg(type_scale);
        #pragma unroll
        for (int c = 0; c < (VPR + TPB - 1) / TPB; ++c) {
            const int idx = c * TPB + tid;
            if (idx < VPR) {
                const int4 pr = __ldg(&pos_table[(size_t)s * VPR + idx]);
                const int4 t0 = __ldg(&type_table[idx]);
                const int4 t1 = __ldg(&type_table[VPR + idx]);
                const float px = (float)pr.x * ps, py = (float)pr.y * ps;
                const float pz = (float)pr.z * ps, pw = (float)pr.w * ps;
                s_pt[0][idx] = make_float4(px + (float)t0.x * ts, py + (float)t0.y * ts,
                                           pz + (float)t0.z * ts, pw + (float)t0.w * ts);
                s_pt[1][idx] = make_float4(px + (float)t1.x * ts, py + (float)t1.y * ts,
                                           pz + (float)t1.z * ts, pw + (float)t1.w * ts);
                s_g[idx] = __ldg(&ln_w[idx]);
                s_b[idx] = __ldg(&ln_b[idx]);
            }
        }
    }
    __syncthreads();   // uniform, once

    const float ws = __ldg(word_scale);

    #pragma unroll
    for (int i = 0; i < TOKW; ++i) {
        const int b = b0 + i;
        if (b >= B) return;
        const int token = b * S + s;

        const int wrow = __ldg(&input_ids[token]);
        const int trow = __ldg(&token_type_ids[token]);

        const int4*   wp = word_table + (size_t)wrow * VPR;
        const float4* pp = s_pt[trow & 1];

        float4 e[CH];
        float sum = 0.f, sq = 0.f;
        #pragma unroll
        for (int c = 0; c < CH; ++c) {
            const int col = c * 32 + lane;
            const int4   w = __ldg(&wp[col]);
            const float4 q = pp[col];       // LDS.128, conflict-free
            e[c].x = (float)w.x * ws + q.x;
            e[c].y = (float)w.y * ws + q.y;
            e[c].z = (float)w.z * ws + q.z;
            e[c].w = (float)w.w * ws + q.w;
            sum += e[c].x + e[c].y + e[c].z + e[c].w;
            sq  += e[c].x * e[c].x + e[c].y * e[c].y
                 + e[c].z * e[c].z + e[c].w * e[c].w;
        }

        // Pure warp reduction (full row lives in this warp).
        #pragma unroll
        for (int off = 16; off > 0; off >>= 1) {
            sum += __shfl_xor_sync(0xFFFFFFFFu, sum, off);
            sq  += __shfl_xor_sync(0xFFFFFFFFu, sq,  off);
        }

        const float inv_h = 1.0f / (float)H;
        const float mean  = sum * inv_h;
        float var = sq * inv_h - mean * mean;
        var = fmaxf(var, 0.0f);

        // The reference's 8-iteration Newton-Raphson sqrt converges to
        // sqrt(var) to full fp32 precision for this data's var range.
        const float std_approx = sqrtf(var);
        const float inv_std = __fdividef(1.0f, std_approx + 1e-12f);

        float4* orow = out + (size_t)token * VPR;
        #pragma unroll
        for (int c = 0; c < CH; ++c) {
            const int col = c * 32 + lane;
            const float4 g = s_g[col];
            const float4 bb = s_b[col];
            float4 o;
            o.x = g.x * ((e[c].x - mean) * inv_std) + bb.x;
            o.y = g.y * ((e[c].y - mean) * inv_std) + bb.y;
            o.z = g.z * ((e[c].z - mean) * inv_std) + bb.z;
            o.w = g.w * ((e[c].w - mean) * inv_std) + bb.w;
            store_streaming(&orow[col], o);
        }
    }
}

extern "C" void kernel_launch(void* const* d_in, const int* in_sizes, int n_in,
                              void* d_out, int out_size)
{
    const int*   input_ids      = (const int*)  d_in[0];
    const int*   token_type_ids = (const int*)  d_in[1];
    const int*   word_table     = (const int*)  d_in[2];
    const float* word_scale     = (const float*)d_in[3];
    const int*   pos_table      = (const int*)  d_in[4];
    const float* pos_scale      = (const float*)d_in[5];
    const int*   type_table     = (const int*)  d_in[6];
    const float* type_scale     = (const float*)d_in[7];
    const float* ln_w           = (const float*)d_in[8];
    const float* ln_b           = (const float*)d_in[9];

    const int n_tokens = in_sizes[0];       // B*S
    const int S        = in_sizes[4] / H;   // 512
    const int B        = n_tokens / S;      // 64

    const int bg   = (B + BPC - 1) / BPC;   // batch groups (4)
    const int grid = S * bg;                // 2048

    bert_emb_ln_kernel<<<grid, TPB>>>(
        input_ids, token_type_ids,
        (const int4*)word_table, word_scale,
        (const int4*)pos_table,  pos_scale,
        (const int4*)type_table, type_scale,
        (const float4*)ln_w, (const float4*)ln_b,
        (float4*)d_out, S, B);
}